// round 1
// baseline (speedup 1.0000x reference)
#include <cuda_runtime.h>
#include <math.h>

#define TX 32
#define TY 16
#define HALO 10
#define KS 11

// Scratch for pooled pyramids (max needed: scale1 = 32*3*192*192 floats each)
__device__ float g_X0[3538944];
__device__ float g_Y0[3538944];
__device__ float g_X1[3538944];
__device__ float g_Y1[3538944];
// Accumulators: [scale][bc][0=ssim_sum,1=cs_sum]
__device__ float g_acc[5 * 96 * 2];

__global__ void zero_acc_kernel() {
    int i = threadIdx.x;
    if (i < 5 * 96 * 2) g_acc[i] = 0.f;
}

// Fused SSIM for one scale. X,Y are [96, W, W]; valid output is OW x OW (OW = W-10).
// Accumulates per-(bc) sums of ssim_map and cs_map into g_acc[scale].
__global__ void ssim_kernel(const float* __restrict__ X, const float* __restrict__ Y,
                            int W, int OW, int scale)
{
    __shared__ float sg[KS];
    __shared__ float sX[TY + HALO][TX + HALO + 2];
    __shared__ float sY[TY + HALO][TX + HALO + 2];
    __shared__ float h0[TY + HALO][TX + 1];
    __shared__ float h1[TY + HALO][TX + 1];
    __shared__ float h2[TY + HALO][TX + 1];
    __shared__ float h3[TY + HALO][TX + 1];
    __shared__ float h4[TY + HALO][TX + 1];
    __shared__ float rs[(TX * TY) / 32], rc[(TX * TY) / 32];

    const int tx = threadIdx.x, ty = threadIdx.y;
    const int t = ty * TX + tx;

    if (t == 0) {
        float tmp[KS];
        float s = 0.f;
        #pragma unroll
        for (int i = 0; i < KS; i++) {
            float c = (float)(i - 5);
            tmp[i] = expf(-(c * c) / 4.5f);
            s += tmp[i];
        }
        #pragma unroll
        for (int i = 0; i < KS; i++) sg[i] = tmp[i] / s;
    }

    const int x0 = blockIdx.x * TX, y0 = blockIdx.y * TY;
    const int bc = blockIdx.z;
    const float* Xb = X + (size_t)bc * W * W;
    const float* Yb = Y + (size_t)bc * W * W;

    // Load input tile (with halo), zero-padding out of range (only feeds invalid outputs)
    for (int idx = t; idx < (TY + HALO) * (TX + HALO); idx += TX * TY) {
        int r = idx / (TX + HALO), c = idx - r * (TX + HALO);
        int gx = x0 + c, gy = y0 + r;
        float xv = 0.f, yv = 0.f;
        if (gx < W && gy < W) {
            xv = Xb[(size_t)gy * W + gx];
            yv = Yb[(size_t)gy * W + gx];
        }
        sX[r][c] = xv;
        sY[r][c] = yv;
    }
    __syncthreads();

    // Horizontal blur of 5 moment maps into shared
    for (int r = ty; r < TY + HALO; r += TY) {
        float a0 = 0.f, a1 = 0.f, a2 = 0.f, a3 = 0.f, a4 = 0.f;
        #pragma unroll
        for (int k = 0; k < KS; k++) {
            float w  = sg[k];
            float xv = sX[r][tx + k];
            float yv = sY[r][tx + k];
            a0 = fmaf(w, xv, a0);
            a1 = fmaf(w, yv, a1);
            a2 = fmaf(w * xv, xv, a2);
            a3 = fmaf(w * yv, yv, a3);
            a4 = fmaf(w * xv, yv, a4);
        }
        h0[r][tx] = a0;
        h1[r][tx] = a1;
        h2[r][tx] = a2;
        h3[r][tx] = a3;
        h4[r][tx] = a4;
    }
    __syncthreads();

    // Vertical blur + SSIM/CS
    float ssum = 0.f, csum = 0.f;
    const int ox = x0 + tx, oy = y0 + ty;
    if (ox < OW && oy < OW) {
        float m1 = 0.f, m2 = 0.f, v1 = 0.f, v2 = 0.f, v12 = 0.f;
        #pragma unroll
        for (int k = 0; k < KS; k++) {
            float w = sg[k];
            m1  = fmaf(w, h0[ty + k][tx], m1);
            m2  = fmaf(w, h1[ty + k][tx], m2);
            v1  = fmaf(w, h2[ty + k][tx], v1);
            v2  = fmaf(w, h3[ty + k][tx], v2);
            v12 = fmaf(w, h4[ty + k][tx], v12);
        }
        const float C1 = 6.5025f, C2 = 58.5225f;
        float mu1sq = m1 * m1, mu2sq = m2 * m2, mu12 = m1 * m2;
        float s1 = v1 - mu1sq, s2 = v2 - mu2sq, s12 = v12 - mu12;
        float cs = (2.f * s12 + C2) / (s1 + s2 + C2);
        float ss = ((2.f * mu12 + C1) / (mu1sq + mu2sq + C1)) * cs;
        ssum = ss;
        csum = cs;
    }

    // Block reduce both sums
    #pragma unroll
    for (int off = 16; off; off >>= 1) {
        ssum += __shfl_down_sync(0xffffffffu, ssum, off);
        csum += __shfl_down_sync(0xffffffffu, csum, off);
    }
    int warp = t >> 5, lane = t & 31;
    if (lane == 0) { rs[warp] = ssum; rc[warp] = csum; }
    __syncthreads();
    if (t == 0) {
        float a = 0.f, b = 0.f;
        #pragma unroll
        for (int i = 0; i < (TX * TY) / 32; i++) { a += rs[i]; b += rc[i]; }
        atomicAdd(&g_acc[(scale * 96 + bc) * 2 + 0], a);
        atomicAdd(&g_acc[(scale * 96 + bc) * 2 + 1], b);
    }
}

// 2x2 avg pool, [96,W,W] -> [96,W/2,W/2]
__global__ void pool_kernel(const float* __restrict__ in, float* __restrict__ out,
                            int W, int n)
{
    int idx = blockIdx.x * blockDim.x + threadIdx.x;
    if (idx >= n) return;
    int ow = W >> 1;
    int bc = idx / (ow * ow);
    int rem = idx - bc * ow * ow;
    int oy = rem / ow, ox = rem - oy * ow;
    const float* p = in + (size_t)bc * W * W + (size_t)(2 * oy) * W + 2 * ox;
    out[idx] = 0.25f * (p[0] + p[1] + p[W] + p[W + 1]);
}

__global__ void finalize_kernel(float* __restrict__ out) {
    __shared__ float sh[96];
    const int i = threadIdx.x;
    const float wts[5]  = {0.0448f, 0.2856f, 0.3001f, 0.2363f, 0.1333f};
    const float cnts[5] = {374.f * 374.f, 182.f * 182.f, 86.f * 86.f, 38.f * 38.f, 14.f * 14.f};
    if (i < 96) {
        float p = 1.f;
        #pragma unroll
        for (int s = 0; s < 5; s++) {
            int comp = (s < 4) ? 1 : 0;  // cs for scales 0..3, ssim for scale 4
            float m = g_acc[(s * 96 + i) * 2 + comp] / cnts[s];
            m = fmaxf(m, 0.f);
            p *= powf(m, wts[s]);
        }
        sh[i] = p;
    }
    __syncthreads();
    if (i == 0) {
        float s = 0.f;
        for (int j = 0; j < 96; j++) s += sh[j];
        out[0] = 1.f - s / 96.f;
    }
}

extern "C" void kernel_launch(void* const* d_in, const int* in_sizes, int n_in,
                              void* d_out, int out_size)
{
    const float* X = (const float*)d_in[0];
    const float* Y = (const float*)d_in[1];
    float* out = (float*)d_out;

    float *X0, *Y0, *X1, *Y1;
    cudaGetSymbolAddress((void**)&X0, g_X0);
    cudaGetSymbolAddress((void**)&Y0, g_Y0);
    cudaGetSymbolAddress((void**)&X1, g_X1);
    cudaGetSymbolAddress((void**)&Y1, g_Y1);

    zero_acc_kernel<<<1, 960>>>();

    dim3 blk(TX, TY);
    auto mkgrid = [](int OW) {
        return dim3((OW + TX - 1) / TX, (OW + TY - 1) / TY, 96);
    };

    // scale 0: 384 -> valid 374
    ssim_kernel<<<mkgrid(374), blk>>>(X, Y, 384, 374, 0);

    int n1 = 96 * 192 * 192;
    pool_kernel<<<(n1 + 255) / 256, 256>>>(X, X0, 384, n1);
    pool_kernel<<<(n1 + 255) / 256, 256>>>(Y, Y0, 384, n1);
    ssim_kernel<<<mkgrid(182), blk>>>(X0, Y0, 192, 182, 1);

    int n2 = 96 * 96 * 96;
    pool_kernel<<<(n2 + 255) / 256, 256>>>(X0, X1, 192, n2);
    pool_kernel<<<(n2 + 255) / 256, 256>>>(Y0, Y1, 192, n2);
    ssim_kernel<<<mkgrid(86), blk>>>(X1, Y1, 96, 86, 2);

    int n3 = 96 * 48 * 48;
    pool_kernel<<<(n3 + 255) / 256, 256>>>(X1, X0, 96, n3);
    pool_kernel<<<(n3 + 255) / 256, 256>>>(Y1, Y0, 96, n3);
    ssim_kernel<<<mkgrid(38), blk>>>(X0, Y0, 48, 38, 3);

    int n4 = 96 * 24 * 24;
    pool_kernel<<<(n4 + 255) / 256, 256>>>(X0, X1, 48, n4);
    pool_kernel<<<(n4 + 255) / 256, 256>>>(Y0, Y1, 48, n4);
    ssim_kernel<<<mkgrid(14), blk>>>(X1, Y1, 24, 14, 4);

    finalize_kernel<<<1, 96>>>(out);
}

// round 2
// speedup vs baseline: 1.9163x; 1.9163x over previous
#include <cuda_runtime.h>
#include <math.h>

#define KS 11
#define TILE 32
#define TYB 8
#define RY 4
#define HR 42   // TILE + 10

typedef unsigned long long ull;

__device__ __forceinline__ ull pk2(float lo, float hi) {
    ull r; asm("mov.b64 %0,{%1,%2};" : "=l"(r) : "f"(lo), "f"(hi)); return r;
}
__device__ __forceinline__ void upk2(ull v, float& lo, float& hi) {
    asm("mov.b64 {%0,%1},%2;" : "=f"(lo), "=f"(hi) : "l"(v));
}
__device__ __forceinline__ ull fma2(ull a, ull b, ull c) {
    ull d; asm("fma.rn.f32x2 %0,%1,%2,%3;" : "=l"(d) : "l"(a), "l"(b), "l"(c)); return d;
}
__device__ __forceinline__ ull mul2(ull a, ull b) {
    ull d; asm("mul.rn.f32x2 %0,%1,%2;" : "=l"(d) : "l"(a), "l"(b)); return d;
}

// Gaussian(sigma=1.5, 11 taps), normalized; computed in double, matches fp32 ref to ~1e-7
__device__ constexpr float GW[KS] = {
    0.00102836f, 0.00759866f, 0.03600077f, 0.10936069f, 0.21300566f,
    0.26601190f,
    0.21300566f, 0.10936069f, 0.03600077f, 0.00759866f, 0.00102836f
};

// Scratch for pooled pyramids (max needed: scale1 = 32*3*192*192 floats each)
__device__ float g_X0[3538944];
__device__ float g_Y0[3538944];
__device__ float g_X1[3538944];
__device__ float g_Y1[3538944];
// Accumulators: [scale][bc][0=ssim_sum,1=cs_sum]
__device__ float g_acc[5 * 96 * 2];

__global__ void zero_acc_kernel() {
    int i = threadIdx.x;
    if (i < 5 * 96 * 2) g_acc[i] = 0.f;
}

__global__ __launch_bounds__(256)
void ssim_kernel(const float* __restrict__ X, const float* __restrict__ Y,
                 int W, int OW, int scale)
{
    __shared__ float2 sXY[HR][HR];     // (x,y) interleaved input tile
    __shared__ float2 h01[HR][TILE];   // (hx, hy)
    __shared__ float2 h23[HR][TILE];   // (hxx, hyy)
    __shared__ float  h4s[HR][TILE];   // hxy
    __shared__ float rs[8], rc[8];

    const int tx = threadIdx.x, ty = threadIdx.y;
    const int t = ty * 32 + tx;
    const int x0 = blockIdx.x * TILE, y0 = blockIdx.y * TILE;
    const int bc = blockIdx.z;
    const float* Xb = X + (size_t)bc * W * W;
    const float* Yb = Y + (size_t)bc * W * W;

    // Load input tile with halo (zero-pad OOB; only feeds discarded outputs)
    for (int idx = t; idx < HR * HR; idx += 256) {
        int r = idx / HR, c = idx - r * HR;
        int gx = x0 + c, gy = y0 + r;
        float xv = 0.f, yv = 0.f;
        if (gx < W && gy < W) {
            size_t o = (size_t)gy * W + gx;
            xv = Xb[o]; yv = Yb[o];
        }
        sXY[r][c] = make_float2(xv, yv);
    }
    __syncthreads();

    ull wpk[KS];
    #pragma unroll
    for (int k = 0; k < KS; k++) wpk[k] = pk2(GW[k], GW[k]);

    // Horizontal blur of 5 moment maps (packed)
    for (int r = ty; r < HR; r += TYB) {
        ull a01 = 0ULL, a23 = 0ULL;
        float a4 = 0.f;
        #pragma unroll
        for (int k = 0; k < KS; k++) {
            float2 v = sXY[r][tx + k];
            ull pv = pk2(v.x, v.y);
            a01 = fma2(pv, wpk[k], a01);        // (w*x, w*y)
            ull vv = mul2(pv, pv);              // (xx, yy)
            a23 = fma2(vv, wpk[k], a23);        // (w*xx, w*yy)
            a4 = fmaf(GW[k] * v.x, v.y, a4);    // w*x*y
        }
        float b0, b1, b2, b3;
        upk2(a01, b0, b1); upk2(a23, b2, b3);
        h01[r][tx] = make_float2(b0, b1);
        h23[r][tx] = make_float2(b2, b3);
        h4s[r][tx] = a4;
    }
    __syncthreads();

    // Vertical blur + SSIM, RY outputs per thread (register sliding window)
    ull amu[RY], asg[RY];
    float axy[RY];
    #pragma unroll
    for (int j = 0; j < RY; j++) { amu[j] = 0ULL; asg[j] = 0ULL; axy[j] = 0.f; }
    const int rbase = ty * RY;
    #pragma unroll
    for (int rr = 0; rr < RY - 1 + KS; rr++) {
        float2 u01 = h01[rbase + rr][tx];
        float2 u23 = h23[rbase + rr][tx];
        float  u4  = h4s[rbase + rr][tx];
        ull p01 = pk2(u01.x, u01.y), p23 = pk2(u23.x, u23.y);
        #pragma unroll
        for (int j = 0; j < RY; j++) {
            int k = rr - j;
            if (k >= 0 && k < KS) {
                amu[j] = fma2(p01, wpk[k], amu[j]);
                asg[j] = fma2(p23, wpk[k], asg[j]);
                axy[j] = fmaf(u4, GW[k], axy[j]);
            }
        }
    }

    float ssum = 0.f, csum = 0.f;
    const int ox = x0 + tx;
    #pragma unroll
    for (int j = 0; j < RY; j++) {
        int oy = y0 + rbase + j;
        if (ox < OW && oy < OW) {
            float m1, m2, v1, v2;
            upk2(amu[j], m1, m2); upk2(asg[j], v1, v2);
            float v12 = axy[j];
            const float C1 = 6.5025f, C2 = 58.5225f;
            float mu1sq = m1 * m1, mu2sq = m2 * m2, mu12 = m1 * m2;
            float s1 = v1 - mu1sq, s2 = v2 - mu2sq, s12 = v12 - mu12;
            float cs = (2.f * s12 + C2) / (s1 + s2 + C2);
            float ss = ((2.f * mu12 + C1) / (mu1sq + mu2sq + C1)) * cs;
            ssum += ss; csum += cs;
        }
    }

    // Block reduce
    #pragma unroll
    for (int off = 16; off; off >>= 1) {
        ssum += __shfl_down_sync(0xffffffffu, ssum, off);
        csum += __shfl_down_sync(0xffffffffu, csum, off);
    }
    int warp = t >> 5, lane = t & 31;
    if (lane == 0) { rs[warp] = ssum; rc[warp] = csum; }
    __syncthreads();
    if (t == 0) {
        float a = 0.f, b = 0.f;
        #pragma unroll
        for (int i = 0; i < 8; i++) { a += rs[i]; b += rc[i]; }
        atomicAdd(&g_acc[(scale * 96 + bc) * 2 + 0], a);
        atomicAdd(&g_acc[(scale * 96 + bc) * 2 + 1], b);
    }
}

// Fused 2x2 avg pool for X and Y (blockIdx.y selects), float4 loads / float2 stores
__global__ void pool2_kernel(const float* __restrict__ inA, const float* __restrict__ inB,
                             float* __restrict__ outA, float* __restrict__ outB,
                             int W, int n2)
{
    int i = blockIdx.x * blockDim.x + threadIdx.x;
    if (i >= n2) return;
    const float* in = blockIdx.y ? inB : inA;
    float* out = blockIdx.y ? outB : outA;
    int ow = W >> 1, owh = ow >> 1;
    int bc = i / (ow * owh);
    int rem = i - bc * ow * owh;
    int oy = rem / owh, oxp = rem - oy * owh;
    const float* p = in + (size_t)bc * W * W + (size_t)(2 * oy) * W + 4 * oxp;
    float4 r0 = *(const float4*)p;
    float4 r1 = *(const float4*)(p + W);
    float2 o;
    o.x = 0.25f * (r0.x + r0.y + r1.x + r1.y);
    o.y = 0.25f * (r0.z + r0.w + r1.z + r1.w);
    *(float2*)(out + (size_t)bc * ow * ow + (size_t)oy * ow + 2 * oxp) = o;
}

__global__ void finalize_kernel(float* __restrict__ out) {
    __shared__ float sh[96];
    const int i = threadIdx.x;
    const float wts[5]  = {0.0448f, 0.2856f, 0.3001f, 0.2363f, 0.1333f};
    const float cnts[5] = {374.f * 374.f, 182.f * 182.f, 86.f * 86.f, 38.f * 38.f, 14.f * 14.f};
    if (i < 96) {
        float p = 1.f;
        #pragma unroll
        for (int s = 0; s < 5; s++) {
            int comp = (s < 4) ? 1 : 0;  // cs for scales 0..3, ssim for scale 4
            float m = g_acc[(s * 96 + i) * 2 + comp] / cnts[s];
            m = fmaxf(m, 0.f);
            p *= powf(m, wts[s]);
        }
        sh[i] = p;
    }
    __syncthreads();
    if (i == 0) {
        float s = 0.f;
        for (int j = 0; j < 96; j++) s += sh[j];
        out[0] = 1.f - s / 96.f;
    }
}

extern "C" void kernel_launch(void* const* d_in, const int* in_sizes, int n_in,
                              void* d_out, int out_size)
{
    const float* X = (const float*)d_in[0];
    const float* Y = (const float*)d_in[1];
    float* out = (float*)d_out;

    float *X0, *Y0, *X1, *Y1;
    cudaGetSymbolAddress((void**)&X0, g_X0);
    cudaGetSymbolAddress((void**)&Y0, g_Y0);
    cudaGetSymbolAddress((void**)&X1, g_X1);
    cudaGetSymbolAddress((void**)&Y1, g_Y1);

    zero_acc_kernel<<<1, 960>>>();

    dim3 blk(32, TYB);
    auto mkgrid = [](int OW) {
        int g = (OW + TILE - 1) / TILE;
        return dim3(g, g, 96);
    };

    // scale 0: 384 -> valid 374
    ssim_kernel<<<mkgrid(374), blk>>>(X, Y, 384, 374, 0);

    int n1 = 96 * 192 * 192 / 2;
    pool2_kernel<<<dim3((n1 + 255) / 256, 2), 256>>>(X, Y, X0, Y0, 384, n1);
    ssim_kernel<<<mkgrid(182), blk>>>(X0, Y0, 192, 182, 1);

    int n2 = 96 * 96 * 96 / 2;
    pool2_kernel<<<dim3((n2 + 255) / 256, 2), 256>>>(X0, Y0, X1, Y1, 192, n2);
    ssim_kernel<<<mkgrid(86), blk>>>(X1, Y1, 96, 86, 2);

    int n3 = 96 * 48 * 48 / 2;
    pool2_kernel<<<dim3((n3 + 255) / 256, 2), 256>>>(X1, Y1, X0, Y0, 96, n3);
    ssim_kernel<<<mkgrid(38), blk>>>(X0, Y0, 48, 38, 3);

    int n4 = 96 * 24 * 24 / 2;
    pool2_kernel<<<dim3((n4 + 255) / 256, 2), 256>>>(X0, Y0, X1, Y1, 48, n4);
    ssim_kernel<<<mkgrid(14), blk>>>(X1, Y1, 24, 14, 4);

    finalize_kernel<<<1, 96>>>(out);
}

// round 3
// speedup vs baseline: 2.1907x; 1.1432x over previous
#include <cuda_runtime.h>
#include <math.h>

#define KS 11
#define TILE 32
#define TYB 8
#define RY 4
#define HR 42   // TILE + 10

typedef unsigned long long ull;

__device__ __forceinline__ ull pk2(float lo, float hi) {
    ull r; asm("mov.b64 %0,{%1,%2};" : "=l"(r) : "f"(lo), "f"(hi)); return r;
}
__device__ __forceinline__ void upk2(ull v, float& lo, float& hi) {
    asm("mov.b64 {%0,%1},%2;" : "=f"(lo), "=f"(hi) : "l"(v));
}
__device__ __forceinline__ ull fma2(ull a, ull b, ull c) {
    ull d; asm("fma.rn.f32x2 %0,%1,%2,%3;" : "=l"(d) : "l"(a), "l"(b), "l"(c)); return d;
}
__device__ __forceinline__ ull mul2(ull a, ull b) {
    ull d; asm("mul.rn.f32x2 %0,%1,%2;" : "=l"(d) : "l"(a), "l"(b)); return d;
}

// Gaussian(sigma=1.5, 11 taps), normalized
__device__ constexpr float GW[KS] = {
    0.00102836f, 0.00759866f, 0.03600077f, 0.10936069f, 0.21300566f,
    0.26601190f,
    0.21300566f, 0.10936069f, 0.03600077f, 0.00759866f, 0.00102836f
};

// Scratch for pooled pyramids
__device__ float g_X0[3538944];
__device__ float g_Y0[3538944];
__device__ float g_X1[3538944];
__device__ float g_Y1[3538944];
// Accumulators: [scale][bc][0=ssim_sum,1=cs_sum]
__device__ float g_acc[5 * 96 * 2];

__global__ void zero_acc_kernel() {
    int i = threadIdx.x;
    if (i < 5 * 96 * 2) g_acc[i] = 0.f;
}

// 4-stream SSIM: blur s=x+y, d=x-y, ss, dd. Two packed f32x2 pipes.
__global__ __launch_bounds__(256)
void ssim_kernel(const float* __restrict__ X, const float* __restrict__ Y,
                 int W, int OW, int scale)
{
    __shared__ float2 sSD[HR][HR];     // (s,d) input tile
    __shared__ float4 sH[HR][TILE];    // (hs, hd, hss, hdd) horizontal-blurred
    __shared__ float rs[8], rc[8];

    const int tx = threadIdx.x, ty = threadIdx.y;
    const int t = ty * 32 + tx;
    const int x0 = blockIdx.x * TILE, y0 = blockIdx.y * TILE;
    const int bc = blockIdx.z;
    const float* Xb = X + (size_t)bc * W * W;
    const float* Yb = Y + (size_t)bc * W * W;

    // Load input tile with halo (zero-pad OOB; only feeds discarded outputs)
    for (int idx = t; idx < HR * HR; idx += 256) {
        int r = idx / HR, c = idx - r * HR;
        int gx = x0 + c, gy = y0 + r;
        float xv = 0.f, yv = 0.f;
        if (gx < W && gy < W) {
            size_t o = (size_t)gy * W + gx;
            xv = Xb[o]; yv = Yb[o];
        }
        sSD[r][c] = make_float2(xv + yv, xv - yv);
    }
    __syncthreads();

    ull wpk[KS];
    #pragma unroll
    for (int k = 0; k < KS; k++) wpk[k] = pk2(GW[k], GW[k]);

    // Horizontal blur: 2 packed streams (s,d) and (ss,dd)
    for (int r = ty; r < HR; r += TYB) {
        ull a01 = 0ULL, a23 = 0ULL;
        #pragma unroll
        for (int k = 0; k < KS; k++) {
            float2 v = sSD[r][tx + k];
            ull pv = pk2(v.x, v.y);
            a01 = fma2(pv, wpk[k], a01);   // (w*s,  w*d)
            ull vv = mul2(pv, pv);         // (ss, dd)
            a23 = fma2(vv, wpk[k], a23);   // (w*ss, w*dd)
        }
        float b0, b1, b2, b3;
        upk2(a01, b0, b1); upk2(a23, b2, b3);
        sH[r][tx] = make_float4(b0, b1, b2, b3);
    }
    __syncthreads();

    // Vertical blur + SSIM, RY outputs per thread
    ull amu[RY], asg[RY];
    #pragma unroll
    for (int j = 0; j < RY; j++) { amu[j] = 0ULL; asg[j] = 0ULL; }
    const int rbase = ty * RY;
    #pragma unroll
    for (int rr = 0; rr < RY - 1 + KS; rr++) {
        float4 u = sH[rbase + rr][tx];
        ull p01 = pk2(u.x, u.y), p23 = pk2(u.z, u.w);
        #pragma unroll
        for (int j = 0; j < RY; j++) {
            int k = rr - j;
            if (k >= 0 && k < KS) {
                amu[j] = fma2(p01, wpk[k], amu[j]);
                asg[j] = fma2(p23, wpk[k], asg[j]);
            }
        }
    }

    float ssum = 0.f, csum = 0.f;
    const int ox = x0 + tx;
    #pragma unroll
    for (int j = 0; j < RY; j++) {
        int oy = y0 + rbase + j;
        if (ox < OW && oy < OW) {
            float ms, md, bss, bdd;
            upk2(amu[j], ms, md); upk2(asg[j], bss, bdd);
            const float C1 = 6.5025f, C2 = 58.5225f;
            float ms2 = ms * ms, md2 = md * md;
            float musum  = 0.5f * (ms2 + md2);          // mu1^2 + mu2^2
            float mu2x   = 0.5f * (ms2 - md2);          // 2*mu1*mu2
            float sqsum  = 0.5f * (bss + bdd);          // blur(xx)+blur(yy)
            float xy2    = 0.5f * (bss - bdd);          // 2*blur(xy)
            float s1s2   = sqsum - musum;               // sigma1^2 + sigma2^2
            float sig122 = xy2 - mu2x;                  // 2*sigma12
            float cs = (sig122 + C2) / (s1s2 + C2);
            float ss = ((mu2x + C1) / (musum + C1)) * cs;
            ssum += ss; csum += cs;
        }
    }

    // Block reduce
    #pragma unroll
    for (int off = 16; off; off >>= 1) {
        ssum += __shfl_down_sync(0xffffffffu, ssum, off);
        csum += __shfl_down_sync(0xffffffffu, csum, off);
    }
    int warp = t >> 5, lane = t & 31;
    if (lane == 0) { rs[warp] = ssum; rc[warp] = csum; }
    __syncthreads();
    if (t == 0) {
        float a = 0.f, b = 0.f;
        #pragma unroll
        for (int i = 0; i < 8; i++) { a += rs[i]; b += rc[i]; }
        atomicAdd(&g_acc[(scale * 96 + bc) * 2 + 0], a);
        atomicAdd(&g_acc[(scale * 96 + bc) * 2 + 1], b);
    }
}

// Fused 2x2 avg pool for X and Y (blockIdx.y selects), float4 loads / float2 stores
__global__ void pool2_kernel(const float* __restrict__ inA, const float* __restrict__ inB,
                             float* __restrict__ outA, float* __restrict__ outB,
                             int W, int n2)
{
    int i = blockIdx.x * blockDim.x + threadIdx.x;
    if (i >= n2) return;
    const float* in = blockIdx.y ? inB : inA;
    float* out = blockIdx.y ? outB : outA;
    int ow = W >> 1, owh = ow >> 1;
    int bc = i / (ow * owh);
    int rem = i - bc * ow * owh;
    int oy = rem / owh, oxp = rem - oy * owh;
    const float* p = in + (size_t)bc * W * W + (size_t)(2 * oy) * W + 4 * oxp;
    float4 r0 = *(const float4*)p;
    float4 r1 = *(const float4*)(p + W);
    float2 o;
    o.x = 0.25f * (r0.x + r0.y + r1.x + r1.y);
    o.y = 0.25f * (r0.z + r0.w + r1.z + r1.w);
    *(float2*)(out + (size_t)bc * ow * ow + (size_t)oy * ow + 2 * oxp) = o;
}

__global__ void finalize_kernel(float* __restrict__ out) {
    __shared__ float sh[96];
    const int i = threadIdx.x;
    const float wts[5]  = {0.0448f, 0.2856f, 0.3001f, 0.2363f, 0.1333f};
    const float cnts[5] = {374.f * 374.f, 182.f * 182.f, 86.f * 86.f, 38.f * 38.f, 14.f * 14.f};
    if (i < 96) {
        float p = 1.f;
        #pragma unroll
        for (int s = 0; s < 5; s++) {
            int comp = (s < 4) ? 1 : 0;
            float m = g_acc[(s * 96 + i) * 2 + comp] / cnts[s];
            m = fmaxf(m, 0.f);
            p *= powf(m, wts[s]);
        }
        sh[i] = p;
    }
    __syncthreads();
    if (i == 0) {
        float s = 0.f;
        for (int j = 0; j < 96; j++) s += sh[j];
        out[0] = 1.f - s / 96.f;
    }
}

extern "C" void kernel_launch(void* const* d_in, const int* in_sizes, int n_in,
                              void* d_out, int out_size)
{
    const float* X = (const float*)d_in[0];
    const float* Y = (const float*)d_in[1];
    float* out = (float*)d_out;

    float *X0, *Y0, *X1, *Y1;
    cudaGetSymbolAddress((void**)&X0, g_X0);
    cudaGetSymbolAddress((void**)&Y0, g_Y0);
    cudaGetSymbolAddress((void**)&X1, g_X1);
    cudaGetSymbolAddress((void**)&Y1, g_Y1);

    zero_acc_kernel<<<1, 960>>>();

    dim3 blk(32, TYB);
    auto mkgrid = [](int OW) {
        int g = (OW + TILE - 1) / TILE;
        return dim3(g, g, 96);
    };

    // scale 0: 384 -> valid 374
    ssim_kernel<<<mkgrid(374), blk>>>(X, Y, 384, 374, 0);

    int n1 = 96 * 192 * 192 / 2;
    pool2_kernel<<<dim3((n1 + 255) / 256, 2), 256>>>(X, Y, X0, Y0, 384, n1);
    ssim_kernel<<<mkgrid(182), blk>>>(X0, Y0, 192, 182, 1);

    int n2 = 96 * 96 * 96 / 2;
    pool2_kernel<<<dim3((n2 + 255) / 256, 2), 256>>>(X0, Y0, X1, Y1, 192, n2);
    ssim_kernel<<<mkgrid(86), blk>>>(X1, Y1, 96, 86, 2);

    int n3 = 96 * 48 * 48 / 2;
    pool2_kernel<<<dim3((n3 + 255) / 256, 2), 256>>>(X1, Y1, X0, Y0, 96, n3);
    ssim_kernel<<<mkgrid(38), blk>>>(X0, Y0, 48, 38, 3);

    int n4 = 96 * 24 * 24 / 2;
    pool2_kernel<<<dim3((n4 + 255) / 256, 2), 256>>>(X0, Y0, X1, Y1, 48, n4);
    ssim_kernel<<<mkgrid(14), blk>>>(X1, Y1, 24, 14, 4);

    finalize_kernel<<<1, 96>>>(out);
}